// round 7
// baseline (speedup 1.0000x reference)
#include <cuda_runtime.h>
#include <cstdint>

#define SEQ    512
#define BATCH  1024
#define NTAG   64
#define NEGINF -10000.0f

__device__ __forceinline__ float ex2f_(float x) {
    float y; asm("ex2.approx.ftz.f32 %0, %1;" : "=f"(y) : "f"(x)); return y;
}
__device__ __forceinline__ float lg2f_(float x) {
    float y; asm("lg2.approx.ftz.f32 %0, %1;" : "=f"(y) : "f"(x)); return y;
}
__device__ __forceinline__ unsigned long long fma2_(unsigned long long a,
                                                    unsigned long long b,
                                                    unsigned long long c) {
    unsigned long long d;
    asm("fma.rn.f32x2 %0, %1, %2, %3;" : "=l"(d) : "l"(a), "l"(b), "l"(c));
    return d;
}
__device__ __forceinline__ unsigned long long add2_(unsigned long long a,
                                                    unsigned long long b) {
    unsigned long long d;
    asm("add.rn.f32x2 %0, %1, %2;" : "=l"(d) : "l"(a), "l"(b));
    return d;
}
__device__ __forceinline__ void unpack_(unsigned long long v, float& x, float& y) {
    asm("mov.b64 {%0, %1}, %2;" : "=f"(x), "=f"(y) : "l"(v));
}
__device__ __forceinline__ unsigned long long pack_(float x, float y) {
    unsigned long long r;
    asm("mov.b64 %0, {%1, %2};" : "=l"(r) : "f"(x), "f"(y));
    return r;
}
__device__ __forceinline__ float wmax_(float v) {
#pragma unroll
    for (int d = 16; d; d >>= 1)
        v = fmaxf(v, __shfl_xor_sync(0xffffffffu, v, d));
    return v;
}

// One warp = one batch, 4 independent warps per CTA. Lane l owns tags (l,l+32).
// LINEAR-space recurrence: p_{s+1} = r * exp(f_s) ∘ (E p_s), scalar log-offset
// C2 (log2 domain). exp(f) is computed in the prefetch pipeline 4 steps ahead;
// renorm factor r = 1/wmax(p) is measured with a 2-step lag. The per-step
// dependency chain contains NO transcendentals: LDS -> 8-deep FFMA2 -> mul ->
// STS -> syncwarp.
__global__ void __launch_bounds__(128)
crf_main(const float* __restrict__ feats,
         const float* __restrict__ mask,
         const float* __restrict__ trans,
         float* __restrict__ out) {
    const int lane = threadIdx.x & 31;
    const int w    = threadIdx.x >> 5;
    const int b    = blockIdx.x * 4 + w;

    __shared__ __align__(16) float pbuf[4][2][NTAG];   // [warp][phase][tag]

    const float LN2 = 0.6931471805599453f;
    const float L2E = 1.4426950408889634f;

    // ---- feats pipeline: raw f (steps 4..7) + ready exp(f) (steps 0..3) ----
    const float* fs    = feats + (size_t)b * NTAG + lane;   // step s at +s*65536
    const float* flast = fs + ((size_t)(SEQ - 1) << 16);
    float efL[4], efH[4], fL[4], fH[4];
#pragma unroll
    for (int u = 0; u < 4; ++u) {
        const float* p0 = fs + ((size_t)u << 16);
        efL[u] = ex2f_(__ldcs(p0) * L2E);
        efH[u] = ex2f_(__ldcs(p0 + 32) * L2E);
        const float* p1 = fs + ((size_t)(u + 4) << 16);
        fL[u] = __ldcs(p1);
        fH[u] = __ldcs(p1 + 32);
    }
    const float* fpre = fs + ((size_t)8 << 16);

    // ---- len = sum of this batch's monotone mask column ----
    float lsum = 0.0f;
#pragma unroll
    for (int t = 0; t < 16; ++t)
        lsum += __ldcs(mask + (size_t)(t * 32 + lane) * BATCH + b);
#pragma unroll
    for (int d = 16; d; d >>= 1)
        lsum += __shfl_xor_sync(0xffffffffu, lsum, d);
    const int len  = (int)(lsum + 0.5f);
    const int lenr = (len + 3) & ~3;

    // ---- E rows for my two tags, packed in i-pairs (one-time exps) ----
    unsigned long long EL[32], EH[32];
    {
        const float4* r0 = reinterpret_cast<const float4*>(trans + lane * NTAG);
        const float4* r1 = reinterpret_cast<const float4*>(trans + (lane + 32) * NTAG);
#pragma unroll
        for (int k = 0; k < 16; ++k) {
            const float4 t0 = r0[k];
            const float4 t1 = r1[k];
            EL[2 * k]     = pack_(__expf(t0.x), __expf(t0.y));  // exp(-1e4) -> 0
            EL[2 * k + 1] = pack_(__expf(t0.z), __expf(t0.w));
            EH[2 * k]     = pack_(__expf(t1.x), __expf(t1.y));
            EH[2 * k + 1] = pack_(__expf(t1.z), __expf(t1.w));
        }
    }
    const float eT_lo = ex2f_(trans[NTAG + lane] * L2E);        // exp(T[END][j])
    const float eT_hi = ex2f_(trans[NTAG + 32 + lane] * L2E);   // (END col -> 0)

    // ---- linear-space state ----
    float p_lo = (lane == 0) ? 1.0f : 0.0f;   // p = exp(alpha0), START=0
    float p_hi = 0.0f;
    float C2   = 0.0f;                        // log2 offset: alpha = (log2 p + C2)*ln2
    float rfac = 1.0f, rfac1 = 1.0f;          // 1/M, lagged 2 steps
    float gC0  = 0.0f, gC1  = 0.0f;           // lg2(M) staged with same lag

    // publish initial p
    pbuf[w][0][lane]      = p_lo;
    pbuf[w][0][lane + 32] = p_hi;
    __syncwarp();

#pragma unroll 1
    for (int s = 0; s < lenr; s += 4) {
#pragma unroll
        for (int u = 0; u < 4; ++u) {
            const int ph = u & 1;

            // S_j = sum_i E[j,i] p_i : 16 LDS.128 broadcast + 64 FFMA2,
            // 8 independent accumulator chains (depth 8)
            const ulonglong2* pb =
                reinterpret_cast<const ulonglong2*>(&pbuf[w][ph][0]);
            unsigned long long x0 = 0ull, x1 = 0ull, x2 = 0ull, x3 = 0ull;
            unsigned long long y0 = 0ull, y1 = 0ull, y2 = 0ull, y3 = 0ull;
#pragma unroll
            for (int k = 0; k < 8; ++k) {
                const ulonglong2 qa = pb[2 * k];
                const ulonglong2 qb = pb[2 * k + 1];
                x0 = fma2_(EL[4 * k],     qa.x, x0);
                x1 = fma2_(EL[4 * k + 1], qa.y, x1);
                y0 = fma2_(EH[4 * k],     qa.x, y0);
                y1 = fma2_(EH[4 * k + 1], qa.y, y1);
                x2 = fma2_(EL[4 * k + 2], qb.x, x2);
                x3 = fma2_(EL[4 * k + 3], qb.y, x3);
                y2 = fma2_(EH[4 * k + 2], qb.x, y2);
                y3 = fma2_(EH[4 * k + 3], qb.y, y3);
            }
            float s0, s1, s2, s3;
            unpack_(add2_(add2_(x0, x1), add2_(x2, x3)), s0, s1);
            unpack_(add2_(add2_(y0, y1), add2_(y2, y3)), s2, s3);

            // p' = r * e^f ∘ S ; freeze past len via select
            const bool upd = (s + u) < len;
            const float n_lo = (s0 + s1) * (efL[u] * rfac);
            const float n_hi = (s2 + s3) * (efH[u] * rfac);
            p_lo = upd ? n_lo : p_lo;
            p_hi = upd ? n_hi : p_hi;
            C2   = upd ? C2 + gC0 : C2;

            // publish for next substep
            pbuf[w][ph ^ 1][lane]      = p_lo;
            pbuf[w][ph ^ 1][lane + 32] = p_hi;
            __syncwarp();

            // ---- off-chain work (consumed >= 2 substeps later) ----
            // feats pipeline: ef for step s+u+4 from raw f loaded 4 ago;
            // raw load for step s+u+8 (clamped)
            efL[u] = ex2f_(fL[u] * L2E);
            efH[u] = ex2f_(fH[u] * L2E);
            const float* pf = (fpre <= flast) ? fpre : flast;
            fL[u] = __ldcs(pf);
            fH[u] = __ldcs(pf + 32);
            fpre += (size_t)1 << 16;

            // renorm pipeline: M = wmax(p) now, applied at substep u+2
            const float M   = fmaxf(wmax_(fmaxf(p_lo, p_hi)), 1e-30f);
            const float lgM = lg2f_(M);
            rfac = rfac1;  gC0 = gC1;
            rfac1 = ex2f_(-lgM);
            gC1   = lgM;
        }
    }

    // out[b] = (C2 + lg2( sum_j p_j * exp(T[END][j]) )) * ln2
    float ss = p_lo * eT_lo + p_hi * eT_hi;
#pragma unroll
    for (int d = 16; d; d >>= 1)
        ss += __shfl_xor_sync(0xffffffffu, ss, d);
    if (lane == 0) out[b] = (C2 + lg2f_(ss)) * LN2;
}

extern "C" void kernel_launch(void* const* d_in, const int* in_sizes, int n_in,
                              void* d_out, int out_size) {
    const float* feats = nullptr;
    const float* maskp = nullptr;
    const float* trans = nullptr;
    for (int i = 0; i < n_in; ++i) {
        if (in_sizes[i] == SEQ * BATCH * NTAG)      feats = (const float*)d_in[i];
        else if (in_sizes[i] == SEQ * BATCH)        maskp = (const float*)d_in[i];
        else if (in_sizes[i] == NTAG * NTAG)        trans = (const float*)d_in[i];
    }
    crf_main<<<BATCH / 4, 128>>>(feats, maskp, trans, (float*)d_out);
}

// round 8
// speedup vs baseline: 1.2002x; 1.2002x over previous
#include <cuda_runtime.h>
#include <cstdint>

#define SEQ    512
#define BATCH  1024
#define NTAG   64

__device__ __forceinline__ float ex2f_(float x) {
    float y; asm("ex2.approx.ftz.f32 %0, %1;" : "=f"(y) : "f"(x)); return y;
}
__device__ __forceinline__ float lg2f_(float x) {
    float y; asm("lg2.approx.ftz.f32 %0, %1;" : "=f"(y) : "f"(x)); return y;
}
__device__ __forceinline__ unsigned long long fma2_(unsigned long long a,
                                                    unsigned long long b,
                                                    unsigned long long c) {
    unsigned long long d;
    asm("fma.rn.f32x2 %0, %1, %2, %3;" : "=l"(d) : "l"(a), "l"(b), "l"(c));
    return d;
}
__device__ __forceinline__ unsigned long long add2_(unsigned long long a,
                                                    unsigned long long b) {
    unsigned long long d;
    asm("add.rn.f32x2 %0, %1, %2;" : "=l"(d) : "l"(a), "l"(b));
    return d;
}
__device__ __forceinline__ void unpack_(unsigned long long v, float& x, float& y) {
    asm("mov.b64 {%0, %1}, %2;" : "=f"(x), "=f"(y) : "l"(v));
}
__device__ __forceinline__ unsigned long long pack_(float x, float y) {
    unsigned long long r;
    asm("mov.b64 %0, {%1, %2};" : "=l"(r) : "f"(x), "f"(y));
    return r;
}
__device__ __forceinline__ float wmax_(float v) {
#pragma unroll
    for (int d = 16; d; d >>= 1)
        v = fmaxf(v, __shfl_xor_sync(0xffffffffu, v, d));
    return v;
}

// One warp = one batch, 4 warps/CTA. Lane l owns tags (l, l+32).
// LINEAR-space recurrence p' = e^{f-SHIFT} ∘ (E p), log2-ledger C2.
// The hot substep contains ONLY: LDS(p) -> FFMA2 matvec -> mul -> STS -> sync.
// No MUFU, no SHFL, no warp reduction per step. Exact renorm once per 4-step
// block: M = wmax(p) measured at substep 3, scale 1/M (+ lg2 M into C2)
// applied at the NEXT block's substep 2 (~3 substeps of slack for the SHFL
// chain). Constant SHIFT keeps drift within ~e^±25 between renorms — safe in
// fp32; flushed tiny p re-enter via the mixing recurrence (error ~1e-6).
__global__ void __launch_bounds__(128)
crf_main(const float* __restrict__ feats,
         const float* __restrict__ mask,
         const float* __restrict__ trans,
         float* __restrict__ out) {
    const int lane = threadIdx.x & 31;
    const int w    = threadIdx.x >> 5;
    const int b    = blockIdx.x * 4 + w;

    __shared__ __align__(16) float pbuf[4][2][NTAG];   // [warp][phase][tag]

    const float LN2 = 0.6931471805599453f;
    const float L2E = 1.4426950408889634f;
    const float SH2 = 6.0f * L2E;     // constant per-step down-scale (log2)

    // ---- feats pipeline: ready e^{f-SHIFT} (steps 0..3) + raw f (4..7) ----
    const float* fs    = feats + (size_t)b * NTAG + lane;   // step s at +s*65536
    const float* flast = fs + ((size_t)(SEQ - 1) << 16);
    float efL[4], efH[4], fL[4], fH[4];
#pragma unroll
    for (int u = 0; u < 4; ++u) {
        const float* p0 = fs + ((size_t)u << 16);
        efL[u] = ex2f_(fmaf(__ldcs(p0),      L2E, -SH2));
        efH[u] = ex2f_(fmaf(__ldcs(p0 + 32), L2E, -SH2));
        const float* p1 = fs + ((size_t)(u + 4) << 16);
        fL[u] = __ldcs(p1);
        fH[u] = __ldcs(p1 + 32);
    }
    const float* fpre = fs + ((size_t)8 << 16);

    // ---- len = sum of this batch's monotone mask column ----
    float lsum = 0.0f;
#pragma unroll
    for (int t = 0; t < 16; ++t)
        lsum += __ldcs(mask + (size_t)(t * 32 + lane) * BATCH + b);
#pragma unroll
    for (int d = 16; d; d >>= 1)
        lsum += __shfl_xor_sync(0xffffffffu, lsum, d);
    const int len  = (int)(lsum + 0.5f);
    const int lenr = (len + 3) & ~3;

    // ---- E rows for my two tags, packed in i-pairs (one-time exps) ----
    unsigned long long EL[32], EH[32];
    {
        const float4* r0 = reinterpret_cast<const float4*>(trans + lane * NTAG);
        const float4* r1 = reinterpret_cast<const float4*>(trans + (lane + 32) * NTAG);
#pragma unroll
        for (int k = 0; k < 16; ++k) {
            const float4 t0 = r0[k];
            const float4 t1 = r1[k];
            EL[2 * k]     = pack_(__expf(t0.x), __expf(t0.y));  // exp(-1e4) -> 0
            EL[2 * k + 1] = pack_(__expf(t0.z), __expf(t0.w));
            EH[2 * k]     = pack_(__expf(t1.x), __expf(t1.y));
            EH[2 * k + 1] = pack_(__expf(t1.z), __expf(t1.w));
        }
    }
    const float eT_lo = ex2f_(trans[NTAG + lane] * L2E);        // exp(T[END][j])
    const float eT_hi = ex2f_(trans[NTAG + 32 + lane] * L2E);

    // ---- linear-space state ----
    float p_lo = (lane == 0) ? 1.0f : 0.0f;   // p = exp(alpha0), START=0
    float p_hi = 0.0f;
    float C2   = 0.0f;                        // alpha = (log2 p + C2) * ln2
    float rfac = 1.0f;                        // renorm scale, applied at u==2
    float lgMp = 0.0f;                        // its lg2(M) ledger entry

    pbuf[w][0][lane]      = p_lo;
    pbuf[w][0][lane + 32] = p_hi;
    __syncwarp();

#pragma unroll 1
    for (int s = 0; s < lenr; s += 4) {
#pragma unroll
        for (int u = 0; u < 4; ++u) {
            const int ph = u & 1;

            // S = E p : 16 LDS.128 broadcast + 64 FFMA2 (8 acc chains)
            const ulonglong2* pb =
                reinterpret_cast<const ulonglong2*>(&pbuf[w][ph][0]);
            unsigned long long x0 = 0ull, x1 = 0ull, x2 = 0ull, x3 = 0ull;
            unsigned long long y0 = 0ull, y1 = 0ull, y2 = 0ull, y3 = 0ull;
#pragma unroll
            for (int k = 0; k < 8; ++k) {
                const ulonglong2 qa = pb[2 * k];
                const ulonglong2 qb = pb[2 * k + 1];
                x0 = fma2_(EL[4 * k],     qa.x, x0);
                x1 = fma2_(EL[4 * k + 1], qa.y, x1);
                y0 = fma2_(EH[4 * k],     qa.x, y0);
                y1 = fma2_(EH[4 * k + 1], qa.y, y1);
                x2 = fma2_(EL[4 * k + 2], qb.x, x2);
                x3 = fma2_(EL[4 * k + 3], qb.y, x3);
                y2 = fma2_(EH[4 * k + 2], qb.x, y2);
                y3 = fma2_(EH[4 * k + 3], qb.y, y3);
            }
            float s0, s1, s2, s3;
            unpack_(add2_(add2_(x0, x1), add2_(x2, x3)), s0, s1);
            unpack_(add2_(add2_(y0, y1), add2_(y2, y3)), s2, s3);

            // p' = e^{f-SHIFT} ∘ S, renorm folded in at substep 2 only
            const bool  upd = (s + u) < len;
            const float fa  = (u == 2) ? efL[u] * rfac : efL[u];
            const float fb  = (u == 2) ? efH[u] * rfac : efH[u];
            const float n_lo = (s0 + s1) * fa;
            const float n_hi = (s2 + s3) * fb;
            p_lo = upd ? n_lo : p_lo;
            p_hi = upd ? n_hi : p_hi;
            C2   = upd ? ((u == 2) ? C2 + SH2 + lgMp : C2 + SH2) : C2;

            pbuf[w][ph ^ 1][lane]      = p_lo;
            pbuf[w][ph ^ 1][lane + 32] = p_hi;
            __syncwarp();

            // off-chain: feats pipeline (consumed 4 substeps later)
            efL[u] = ex2f_(fmaf(fL[u], L2E, -SH2));
            efH[u] = ex2f_(fmaf(fH[u], L2E, -SH2));
            const float* pf = (fpre <= flast) ? fpre : flast;
            fL[u] = __ldcs(pf);
            fH[u] = __ldcs(pf + 32);
            fpre += (size_t)1 << 16;

            // once per block: measure renorm, applied next block (3-substep slack)
            if (u == 3) {
                const float M   = fmaxf(wmax_(fmaxf(p_lo, p_hi)), 1e-30f);
                const float lgM = lg2f_(M);
                rfac = ex2f_(-lgM);
                lgMp = lgM;
            }
        }
    }

    // out[b] = (C2 + lg2( sum_j p_j * exp(T[END][j]) )) * ln2
    float ss = p_lo * eT_lo + p_hi * eT_hi;
#pragma unroll
    for (int d = 16; d; d >>= 1)
        ss += __shfl_xor_sync(0xffffffffu, ss, d);
    if (lane == 0) out[b] = (C2 + lg2f_(ss)) * LN2;
}

extern "C" void kernel_launch(void* const* d_in, const int* in_sizes, int n_in,
                              void* d_out, int out_size) {
    const float* feats = nullptr;
    const float* maskp = nullptr;
    const float* trans = nullptr;
    for (int i = 0; i < n_in; ++i) {
        if (in_sizes[i] == SEQ * BATCH * NTAG)      feats = (const float*)d_in[i];
        else if (in_sizes[i] == SEQ * BATCH)        maskp = (const float*)d_in[i];
        else if (in_sizes[i] == NTAG * NTAG)        trans = (const float*)d_in[i];
    }
    crf_main<<<BATCH / 4, 128>>>(feats, maskp, trans, (float*)d_out);
}

// round 9
// speedup vs baseline: 1.2043x; 1.0034x over previous
#include <cuda_runtime.h>
#include <cstdint>

#define SEQ    512
#define BATCH  1024
#define NTAG   64

__device__ __forceinline__ float ex2f_(float x) {
    float y; asm("ex2.approx.ftz.f32 %0, %1;" : "=f"(y) : "f"(x)); return y;
}
__device__ __forceinline__ float lg2f_(float x) {
    float y; asm("lg2.approx.ftz.f32 %0, %1;" : "=f"(y) : "f"(x)); return y;
}
__device__ __forceinline__ unsigned long long fma2_(unsigned long long a,
                                                    unsigned long long b,
                                                    unsigned long long c) {
    unsigned long long d;
    asm("fma.rn.f32x2 %0, %1, %2, %3;" : "=l"(d) : "l"(a), "l"(b), "l"(c));
    return d;
}
__device__ __forceinline__ unsigned long long add2_(unsigned long long a,
                                                    unsigned long long b) {
    unsigned long long d;
    asm("add.rn.f32x2 %0, %1, %2;" : "=l"(d) : "l"(a), "l"(b));
    return d;
}
__device__ __forceinline__ void unpack_(unsigned long long v, float& x, float& y) {
    asm("mov.b64 {%0, %1}, %2;" : "=f"(x), "=f"(y) : "l"(v));
}
__device__ __forceinline__ unsigned long long pack_(float x, float y) {
    unsigned long long r;
    asm("mov.b64 %0, {%1, %2};" : "=l"(r) : "f"(x), "f"(y));
    return r;
}
__device__ __forceinline__ float wmax_(float v) {
#pragma unroll
    for (int d = 16; d; d >>= 1)
        v = fmaxf(v, __shfl_xor_sync(0xffffffffu, v, d));
    return v;
}

// One warp = one batch, 4 warps/CTA. Lane l owns tags (l, l+32).
// LINEAR-space recurrence p' = e^{f-SHIFT} ∘ (E p), log2-ledger C2.
// The hot substep contains ONLY: LDS(p) -> FFMA2 matvec -> mul -> STS -> sync.
// No MUFU, no SHFL, no warp reduction per step. Exact renorm once per 4-step
// block: M = wmax(p) measured at substep 3, scale 1/M (+ lg2 M into C2)
// applied at the NEXT block's substep 2 (~3 substeps of slack for the SHFL
// chain). Constant SHIFT keeps drift within ~e^±25 between renorms — safe in
// fp32; flushed tiny p re-enter via the mixing recurrence (error ~1e-6).
__global__ void __launch_bounds__(128)
crf_main(const float* __restrict__ feats,
         const float* __restrict__ mask,
         const float* __restrict__ trans,
         float* __restrict__ out) {
    const int lane = threadIdx.x & 31;
    const int w    = threadIdx.x >> 5;
    const int b    = blockIdx.x * 4 + w;

    __shared__ __align__(16) float pbuf[4][2][NTAG];   // [warp][phase][tag]

    const float LN2 = 0.6931471805599453f;
    const float L2E = 1.4426950408889634f;
    const float SH2 = 6.0f * L2E;     // constant per-step down-scale (log2)

    // ---- feats pipeline: ready e^{f-SHIFT} (steps 0..3) + raw f (4..7) ----
    const float* fs    = feats + (size_t)b * NTAG + lane;   // step s at +s*65536
    const float* flast = fs + ((size_t)(SEQ - 1) << 16);
    float efL[4], efH[4], fL[4], fH[4];
#pragma unroll
    for (int u = 0; u < 4; ++u) {
        const float* p0 = fs + ((size_t)u << 16);
        efL[u] = ex2f_(fmaf(__ldcs(p0),      L2E, -SH2));
        efH[u] = ex2f_(fmaf(__ldcs(p0 + 32), L2E, -SH2));
        const float* p1 = fs + ((size_t)(u + 4) << 16);
        fL[u] = __ldcs(p1);
        fH[u] = __ldcs(p1 + 32);
    }
    const float* fpre = fs + ((size_t)8 << 16);

    // ---- len = sum of this batch's monotone mask column ----
    float lsum = 0.0f;
#pragma unroll
    for (int t = 0; t < 16; ++t)
        lsum += __ldcs(mask + (size_t)(t * 32 + lane) * BATCH + b);
#pragma unroll
    for (int d = 16; d; d >>= 1)
        lsum += __shfl_xor_sync(0xffffffffu, lsum, d);
    const int len  = (int)(lsum + 0.5f);
    const int lenr = (len + 3) & ~3;

    // ---- E rows for my two tags, packed in i-pairs (one-time exps) ----
    unsigned long long EL[32], EH[32];
    {
        const float4* r0 = reinterpret_cast<const float4*>(trans + lane * NTAG);
        const float4* r1 = reinterpret_cast<const float4*>(trans + (lane + 32) * NTAG);
#pragma unroll
        for (int k = 0; k < 16; ++k) {
            const float4 t0 = r0[k];
            const float4 t1 = r1[k];
            EL[2 * k]     = pack_(__expf(t0.x), __expf(t0.y));  // exp(-1e4) -> 0
            EL[2 * k + 1] = pack_(__expf(t0.z), __expf(t0.w));
            EH[2 * k]     = pack_(__expf(t1.x), __expf(t1.y));
            EH[2 * k + 1] = pack_(__expf(t1.z), __expf(t1.w));
        }
    }
    const float eT_lo = ex2f_(trans[NTAG + lane] * L2E);        // exp(T[END][j])
    const float eT_hi = ex2f_(trans[NTAG + 32 + lane] * L2E);

    // ---- linear-space state ----
    float p_lo = (lane == 0) ? 1.0f : 0.0f;   // p = exp(alpha0), START=0
    float p_hi = 0.0f;
    float C2   = 0.0f;                        // alpha = (log2 p + C2) * ln2
    float rfac = 1.0f;                        // renorm scale, applied at u==2
    float lgMp = 0.0f;                        // its lg2(M) ledger entry

    pbuf[w][0][lane]      = p_lo;
    pbuf[w][0][lane + 32] = p_hi;
    __syncwarp();

#pragma unroll 1
    for (int s = 0; s < lenr; s += 4) {
#pragma unroll
        for (int u = 0; u < 4; ++u) {
            const int ph = u & 1;

            // S = E p : 16 LDS.128 broadcast + 64 FFMA2 (8 acc chains)
            const ulonglong2* pb =
                reinterpret_cast<const ulonglong2*>(&pbuf[w][ph][0]);
            unsigned long long x0 = 0ull, x1 = 0ull, x2 = 0ull, x3 = 0ull;
            unsigned long long y0 = 0ull, y1 = 0ull, y2 = 0ull, y3 = 0ull;
#pragma unroll
            for (int k = 0; k < 8; ++k) {
                const ulonglong2 qa = pb[2 * k];
                const ulonglong2 qb = pb[2 * k + 1];
                x0 = fma2_(EL[4 * k],     qa.x, x0);
                x1 = fma2_(EL[4 * k + 1], qa.y, x1);
                y0 = fma2_(EH[4 * k],     qa.x, y0);
                y1 = fma2_(EH[4 * k + 1], qa.y, y1);
                x2 = fma2_(EL[4 * k + 2], qb.x, x2);
                x3 = fma2_(EL[4 * k + 3], qb.y, x3);
                y2 = fma2_(EH[4 * k + 2], qb.x, y2);
                y3 = fma2_(EH[4 * k + 3], qb.y, y3);
            }
            float s0, s1, s2, s3;
            unpack_(add2_(add2_(x0, x1), add2_(x2, x3)), s0, s1);
            unpack_(add2_(add2_(y0, y1), add2_(y2, y3)), s2, s3);

            // p' = e^{f-SHIFT} ∘ S, renorm folded in at substep 2 only
            const bool  upd = (s + u) < len;
            const float fa  = (u == 2) ? efL[u] * rfac : efL[u];
            const float fb  = (u == 2) ? efH[u] * rfac : efH[u];
            const float n_lo = (s0 + s1) * fa;
            const float n_hi = (s2 + s3) * fb;
            p_lo = upd ? n_lo : p_lo;
            p_hi = upd ? n_hi : p_hi;
            C2   = upd ? ((u == 2) ? C2 + SH2 + lgMp : C2 + SH2) : C2;

            pbuf[w][ph ^ 1][lane]      = p_lo;
            pbuf[w][ph ^ 1][lane + 32] = p_hi;
            __syncwarp();

            // off-chain: feats pipeline (consumed 4 substeps later)
            efL[u] = ex2f_(fmaf(fL[u], L2E, -SH2));
            efH[u] = ex2f_(fmaf(fH[u], L2E, -SH2));
            const float* pf = (fpre <= flast) ? fpre : flast;
            fL[u] = __ldcs(pf);
            fH[u] = __ldcs(pf + 32);
            fpre += (size_t)1 << 16;

            // once per block: measure renorm, applied next block (3-substep slack)
            if (u == 3) {
                const float M   = fmaxf(wmax_(fmaxf(p_lo, p_hi)), 1e-30f);
                const float lgM = lg2f_(M);
                rfac = ex2f_(-lgM);
                lgMp = lgM;
            }
        }
    }

    // out[b] = (C2 + lg2( sum_j p_j * exp(T[END][j]) )) * ln2
    float ss = p_lo * eT_lo + p_hi * eT_hi;
#pragma unroll
    for (int d = 16; d; d >>= 1)
        ss += __shfl_xor_sync(0xffffffffu, ss, d);
    if (lane == 0) out[b] = (C2 + lg2f_(ss)) * LN2;
}

extern "C" void kernel_launch(void* const* d_in, const int* in_sizes, int n_in,
                              void* d_out, int out_size) {
    const float* feats = nullptr;
    const float* maskp = nullptr;
    const float* trans = nullptr;
    for (int i = 0; i < n_in; ++i) {
        if (in_sizes[i] == SEQ * BATCH * NTAG)      feats = (const float*)d_in[i];
        else if (in_sizes[i] == SEQ * BATCH)        maskp = (const float*)d_in[i];
        else if (in_sizes[i] == NTAG * NTAG)        trans = (const float*)d_in[i];
    }
    crf_main<<<BATCH / 4, 128>>>(feats, maskp, trans, (float*)d_out);
}